// round 13
// baseline (speedup 1.0000x reference)
#include <cuda_runtime.h>
#include <cuda_fp16.h>
#include <cstdint>
#include <math.h>

typedef __half f16;

// ---------------- problem dims ----------------
#define Bn 64
#define Nn 256
#define Fn 16
#define Hn 256
#define ROWS (Bn*Nn)          // 16384
#define N_ITERS 10
#define PLANE (ROWS*Hn)       // 4194304
#define NBLK 256              // persistent grid = (2,128)

// ---------------- scratch ----------------
__device__ float g_h  [PLANE];
__device__ float g_z  [PLANE];
__device__ float g_jcz[PLANE];
__device__ float g_jcr[PLANE];
__device__ float g_jch[PLANE];
__device__ float g_t2 [PLANE];
__device__ f16 g_hP [2*PLANE];
__device__ f16 g_tP [2*PLANE];
__device__ f16 g_mP [2*PLANE];
__device__ f16 g_rhP[2*PLANE];
__device__ f16 g_daP[2*PLANE];
#define WOFF_MSG 0
#define WOFF_ZR  65536
#define WOFF_HB  327680
#define WOFF_R1  458752
#define WOFF_R2  524288
#define WTOTAL   589824
__device__ f16 g_wH[WTOTAL];
__device__ f16 g_wL[WTOTAL];

// grid barrier state
__device__ int g_bar_count;
__device__ unsigned int g_bar_gen;

__device__ __forceinline__ float sigf(float x) { return 1.0f / (1.0f + expf(-x)); }

__device__ __forceinline__ uint32_t smem_u32(const void* p) {
    return (uint32_t)__cvta_generic_to_shared(p);
}
#define CP16(dst, src) asm volatile("cp.async.cg.shared.global [%0], [%1], 16;" :: "r"(dst), "l"(src))
#define CP_COMMIT()    asm volatile("cp.async.commit_group;" ::: "memory")
#define CP_WAIT(n)     asm volatile("cp.async.wait_group %0;" :: "n"(n) : "memory")

__device__ __forceinline__ float2 ldcg2(const float* p) {
    float2 v; asm volatile("ld.global.cg.v2.f32 {%0,%1}, [%2];" : "=f"(v.x), "=f"(v.y) : "l"(p)); return v;
}
__device__ __forceinline__ float ldcg1(const float* p) {
    float v; asm volatile("ld.global.cg.f32 %0, [%1];" : "=f"(v) : "l"(p)); return v;
}

__device__ __forceinline__ void grid_barrier() {
    __syncthreads();
    if (threadIdx.x == 0) {
        __threadfence();   // release: make this CTA's STGs visible at device scope
        volatile unsigned int* genp = &g_bar_gen;
        unsigned int gen = *genp;
        if (atomicAdd(&g_bar_count, 1) == NBLK - 1) {
            g_bar_count = 0;
            __threadfence();
            atomicAdd(&g_bar_gen, 1);
        } else {
            while (*genp == gen) { __nanosleep(64); }
        }
        __threadfence();   // acquire
    }
    __syncthreads();
}

__device__ __forceinline__ void split1(float v, f16& h, f16& l) {
    h = __float2half_rn(v);
    l = __float2half_rn(v - __half2float(h));
}
__device__ __forceinline__ void store_planes(f16* Ph, f16* Pl, size_t idx, float4 v) {
    __half2 h01 = __floats2half2_rn(v.x, v.y);
    __half2 h23 = __floats2half2_rn(v.z, v.w);
    float r0 = v.x - __low2float(h01), r1 = v.y - __high2float(h01);
    float r2 = v.z - __low2float(h23), r3 = v.w - __high2float(h23);
    __half2 l01 = __floats2half2_rn(r0, r1);
    __half2 l23 = __floats2half2_rn(r2, r3);
    uint2 hv, lv;
    hv.x = *(uint32_t*)&h01; hv.y = *(uint32_t*)&h23;
    lv.x = *(uint32_t*)&l01; lv.y = *(uint32_t*)&l23;
    *(uint2*)(Ph + idx) = hv;
    *(uint2*)(Pl + idx) = lv;
}
__device__ __forceinline__ void store_planes2(f16* Ph, f16* Pl, size_t idx, float2 v) {
    __half2 h = __floats2half2_rn(v.x, v.y);
    float r0 = v.x - __low2float(h), r1 = v.y - __high2float(h);
    __half2 l = __floats2half2_rn(r0, r1);
    *(uint32_t*)(Ph + idx) = *(uint32_t*)&h;
    *(uint32_t*)(Pl + idx) = *(uint32_t*)&l;
}
__device__ __forceinline__ void store_hi2(f16* Ph, size_t idx, float2 v) {
    __half2 h = __floats2half2_rn(v.x, v.y);
    *(uint32_t*)(Ph + idx) = *(uint32_t*)&h;
}

// ---------------- raw mma helpers ----------------
__device__ __forceinline__ void ldsm4(uint32_t addr, uint32_t& r0, uint32_t& r1, uint32_t& r2, uint32_t& r3) {
    asm volatile("ldmatrix.sync.aligned.m8n8.x4.shared.b16 {%0,%1,%2,%3}, [%4];"
                 : "=r"(r0), "=r"(r1), "=r"(r2), "=r"(r3) : "r"(addr));
}
__device__ __forceinline__ void ldsm4t(uint32_t addr, uint32_t& r0, uint32_t& r1, uint32_t& r2, uint32_t& r3) {
    asm volatile("ldmatrix.sync.aligned.m8n8.x4.trans.shared.b16 {%0,%1,%2,%3}, [%4];"
                 : "=r"(r0), "=r"(r1), "=r"(r2), "=r"(r3) : "r"(addr));
}
__device__ __forceinline__ void mma16816(float* d, const uint32_t* a, const uint32_t* b) {
    asm volatile("mma.sync.aligned.m16n8k16.row.col.f32.f16.f16.f32 "
                 "{%0,%1,%2,%3}, {%4,%5,%6,%7}, {%8,%9}, {%0,%1,%2,%3};"
                 : "+f"(d[0]), "+f"(d[1]), "+f"(d[2]), "+f"(d[3])
                 : "r"(a[0]), "r"(a[1]), "r"(a[2]), "r"(a[3]), "r"(b[0]), "r"(b[1]));
}

// ---------------- GEMM stage (device function) ----------------
enum { EPI_T = 0, EPI_M, EPI_Z, EPI_R, EPI_GRU, EPI_R1, EPI_R2 };

#define STAGES 3
#define LDA 40
#define LDB 136
#define AHI_OFF 0
#define ALO_OFF 10240
#define BHI_OFF 20480
#define BLO_OFF 29184
#define STAGE_BYTES 37888
#define SMEM_BYTES (STAGES*STAGE_BYTES)   // 113664 (x2 CTA/SM = 227328 <= 228KB)

template<int EPI, int PASSES>
__device__ void gemm_stage(
        const uint32_t smaddr,
        const f16* __restrict__ A0h, const f16* __restrict__ A0l,
        const f16* __restrict__ A1h, const f16* __restrict__ A1l,
        const f16* __restrict__ Bh,  const f16* __restrict__ Bl,
        int NB, int K, int batched,
        const float* __restrict__ bias,
        const float* __restrict__ jc,
        const float* __restrict__ Hb,  const float* __restrict__ Zb,
        float* Cf, f16* Ch, f16* Cl)
{
    const int tid = threadIdx.x, wid = tid >> 5, lane = tid & 31;
    const int bn = blockIdx.x * 128, bm = blockIdx.y * 128;
    const int warp_m = wid >> 2;
    const int warp_n = wid & 3;

    int am = bm;
    size_t aoff = 0, boff = 0;
    if (batched) {
        const int b = bm >> 8;
        aoff = (size_t)b * (Nn * Hn);
        boff = (size_t)b * (Nn * Hn);
        am = bm & (Nn - 1);
    }

    const int NC = K >> 5;

    auto issue = [&](int kb) {
        const int buf = kb % STAGES;
        const uint32_t sb = smaddr + buf * STAGE_BYTES;
        const int kk = (kb & 7) * 32;
        const f16 *ah, *al; int arow;
        if (kb < 8) { ah = A0h + aoff; al = A0l + aoff; arow = am; }
        else        { ah = A1h;        al = A1l;        arow = bm; }
        #pragma unroll
        for (int i = 0; i < 2; i++) {
            const int c = tid + i * 256;
            {
                const int r = c >> 2, c8 = (c & 3) * 8;
                const f16* s1 = ah + (size_t)(arow + r) * Hn + kk + c8;
                const uint32_t d = smaddr + (buf * STAGE_BYTES) + AHI_OFF + (uint32_t)(r * LDA + c8) * 2;
                CP16(d, s1);
                if (PASSES >= 2) {
                    const f16* s2 = al + (size_t)(arow + r) * Hn + kk + c8;
                    CP16(d + (ALO_OFF - AHI_OFF), s2);
                }
            }
            {
                const int r = c >> 4, c8 = (c & 15) * 8;
                const f16* s1 = Bh + boff + (size_t)(kb * 32 + r) * NB + bn + c8;
                const uint32_t d = sb + BHI_OFF + (uint32_t)(r * LDB + c8) * 2;
                CP16(d, s1);
                if (PASSES == 3) {
                    const f16* s2 = Bl + boff + (size_t)(kb * 32 + r) * NB + bn + c8;
                    CP16(d + (BLO_OFF - BHI_OFF), s2);
                }
            }
        }
    };

    float acc[4][4][4];
    #pragma unroll
    for (int mi = 0; mi < 4; mi++)
        #pragma unroll
        for (int nj = 0; nj < 4; nj++)
            #pragma unroll
            for (int q = 0; q < 4; q++) acc[mi][nj][q] = 0.0f;

    const uint32_t a_lrow = (uint32_t)(lane & 15);
    const uint32_t a_lcol = (uint32_t)((lane >> 4) << 3);
    const uint32_t b_lrow = (uint32_t)(lane & 15);
    const uint32_t b_lcol = (uint32_t)((lane >> 4) << 3);

    CP_WAIT(0);               // no stale groups from previous stage
    issue(0); CP_COMMIT();
    if (NC > 1) issue(1);
    CP_COMMIT();

    for (int kb = 0; kb < NC; kb++) {
        CP_WAIT(1);
        __syncthreads();

        if (kb + STAGES - 1 < NC) issue(kb + STAGES - 1);
        CP_COMMIT();

        const uint32_t sb = smaddr + (kb % STAGES) * STAGE_BYTES;

        #pragma unroll
        for (int kk = 0; kk < 2; kk++) {
            const uint32_t brow = (uint32_t)(kk * 16) + b_lrow;
            const uint32_t bcol0 = (uint32_t)(warp_n * 32) + b_lcol;
            uint32_t bfr[8];
            {   // B_hi
                const uint32_t ba = sb + BHI_OFF + (brow * LDB + bcol0) * 2;
                ldsm4t(ba,      bfr[0], bfr[1], bfr[2], bfr[3]);
                ldsm4t(ba + 32, bfr[4], bfr[5], bfr[6], bfr[7]);
            }
            const uint32_t arow0 = (uint32_t)(warp_m * 64) + a_lrow;
            const uint32_t acol = (uint32_t)(kk * 16) + a_lcol;
            // ---- pass 1: A_hi x B_hi ----
            #pragma unroll
            for (int mi = 0; mi < 4; mi++) {
                uint32_t a[4];
                ldsm4(sb + AHI_OFF + ((arow0 + mi * 16) * LDA + acol) * 2, a[0], a[1], a[2], a[3]);
                #pragma unroll
                for (int nj = 0; nj < 4; nj++) mma16816(acc[mi][nj], a, &bfr[nj * 2]);
            }
            // ---- pass 2: A_lo x B_hi ----
            if (PASSES >= 2) {
                #pragma unroll
                for (int mi = 0; mi < 4; mi++) {
                    uint32_t a[4];
                    ldsm4(sb + ALO_OFF + ((arow0 + mi * 16) * LDA + acol) * 2, a[0], a[1], a[2], a[3]);
                    #pragma unroll
                    for (int nj = 0; nj < 4; nj++) mma16816(acc[mi][nj], a, &bfr[nj * 2]);
                }
            }
            // ---- pass 3: A_hi x B_lo ----
            if (PASSES == 3) {
                const uint32_t ba = sb + BLO_OFF + (brow * LDB + bcol0) * 2;
                ldsm4t(ba,      bfr[0], bfr[1], bfr[2], bfr[3]);
                ldsm4t(ba + 32, bfr[4], bfr[5], bfr[6], bfr[7]);
                #pragma unroll
                for (int mi = 0; mi < 4; mi++) {
                    uint32_t a[4];
                    ldsm4(sb + AHI_OFF + ((arow0 + mi * 16) * LDA + acol) * 2, a[0], a[1], a[2], a[3]);
                    #pragma unroll
                    for (int nj = 0; nj < 4; nj++) mma16816(acc[mi][nj], a, &bfr[nj * 2]);
                }
            }
        }
    }

    // ---------------- register-direct epilogue ----------------
    // NOTE: persistent kernel — rewritten fp32 inputs (h, z) must bypass L1 (.cg).
    const int r_in = lane >> 2;
    const int c_in = (lane & 3) * 2;

    #pragma unroll
    for (int mi = 0; mi < 4; mi++) {
        #pragma unroll
        for (int nj = 0; nj < 4; nj++) {
            #pragma unroll
            for (int half = 0; half < 2; half++) {
                const int row = bm + warp_m * 64 + mi * 16 + r_in + half * 8;
                const int col = bn + warp_n * 32 + nj * 8 + c_in;
                float2 v = make_float2(acc[mi][nj][half * 2], acc[mi][nj][half * 2 + 1]);
                const size_t idx = (size_t)row * Hn + col;

                if (EPI == EPI_T) {
                    float2 bv = *(const float2*)(bias + col);
                    v.x += bv.x; v.y += bv.y;
                    store_hi2(Ch, idx, v);
                } else if (EPI == EPI_R1) {
                    float2 bv = *(const float2*)(bias + col);
                    v.x = tanhf(v.x + bv.x); v.y = tanhf(v.y + bv.y);
                    store_planes2(Ch, Cl, idx, v);
                } else if (EPI == EPI_M) {
                    v.x = tanhf(v.x); v.y = tanhf(v.y);
                    store_planes2(Ch, Cl, idx, v);
                } else if (EPI == EPI_Z) {
                    float2 jv = *(const float2*)(jc + idx);
                    v.x = sigf(v.x + jv.x); v.y = sigf(v.y + jv.y);
                    *(float2*)(Cf + idx) = v;
                } else if (EPI == EPI_R) {
                    float2 jv = *(const float2*)(jc + idx);
                    float2 hv = ldcg2(Hb + idx);
                    v.x = sigf(v.x + jv.x) * hv.x;
                    v.y = sigf(v.y + jv.y) * hv.y;
                    store_planes2(Ch, Cl, idx, v);
                } else if (EPI == EPI_GRU) {
                    float2 jv = *(const float2*)(jc + idx);
                    float2 hv = ldcg2(Hb + idx);
                    float2 zv = ldcg2(Zb + idx);
                    float t0 = tanhf(v.x + jv.x), t1 = tanhf(v.y + jv.y);
                    v.x = hv.x + zv.x * (t0 - hv.x);
                    v.y = hv.y + zv.y * (t1 - hv.y);
                    *(float2*)(Cf + idx) = v;
                    store_hi2(Ch, idx, v);
                } else if (EPI == EPI_R2) {
                    float2 bv = *(const float2*)(bias + col);
                    v.x += bv.x; v.y += bv.y;
                    *(float2*)(Cf + idx) = v;
                }
            }
        }
    }
}

// ---------------- persistent kernel: all 52 GEMM stages + reduce ----------------
__global__ void __launch_bounds__(256, 2) mpnn_persist(
    const float* __restrict__ b_msg, const float* __restrict__ b_r1, const float* __restrict__ b_r2,
    float* __restrict__ out)
{
    extern __shared__ char sm[];
    const uint32_t smaddr = smem_u32(sm);

    float* h   = g_h;   float* z = g_z;
    float* jcz = g_jcz; float* jcr = g_jcr; float* jch = g_jch;
    float* t2  = g_t2;
    f16 *hPh = g_hP,  *hPl = g_hP + PLANE;
    f16 *tPh = g_tP,  *tPl = g_tP + PLANE;
    f16 *mPh = g_mP,  *mPl = g_mP + PLANE;
    f16 *rhPh = g_rhP, *rhPl = g_rhP + PLANE;
    f16 *daPh = g_daP, *daPl = g_daP + PLANE;
    f16 *wH = g_wH, *wL = g_wL;

    for (int it = 0; it < N_ITERS; it++) {
        // t = h @ W_msg + b_msg (1-pass)
        gemm_stage<EPI_T,1>(smaddr, hPh, hPl, nullptr, nullptr,
            wH + WOFF_MSG, wL + WOFF_MSG, 256, 256, 0,
            b_msg, nullptr, nullptr, nullptr, nullptr, tPh, tPl);
        grid_barrier();
        // m = tanh(dads @ t) (1-pass, batched)
        gemm_stage<EPI_M,1>(smaddr, daPh, daPl, nullptr, nullptr,
            tPh, tPl, 256, 256, 1,
            nullptr, nullptr, nullptr, nullptr, nullptr, mPh, mPl);
        grid_barrier();
        // z gate (1-pass)
        gemm_stage<EPI_Z,1>(smaddr, mPh, mPl, hPh, hPl,
            wH + WOFF_ZR, wL + WOFF_ZR, 512, 512, 0,
            nullptr, jcz, nullptr, nullptr, z, nullptr, nullptr);
        grid_barrier();
        // r gate -> rh planes (1-pass)
        gemm_stage<EPI_R,1>(smaddr, mPh, mPl, hPh, hPl,
            wH + WOFF_ZR + 256, wL + WOFF_ZR + 256, 512, 512, 0,
            nullptr, jcr, h, nullptr, nullptr, rhPh, rhPl);
        grid_barrier();
        // GRU update (2-pass)
        gemm_stage<EPI_GRU,2>(smaddr, mPh, mPl, rhPh, rhPl,
            wH + WOFF_HB, wL + WOFF_HB, 256, 512, 0,
            nullptr, jch, h, z, h, hPh, hPl);
        grid_barrier();
    }

    // readout (R1 1-pass: hPl is identically zero -> same result as 2-pass)
    gemm_stage<EPI_R1,1>(smaddr, hPh, hPl, nullptr, nullptr,
        wH + WOFF_R1, wL + WOFF_R1, 256, 256, 0,
        b_r1, nullptr, nullptr, nullptr, nullptr, tPh, tPl);
    grid_barrier();
    gemm_stage<EPI_R2,2>(smaddr, tPh, tPl, nullptr, nullptr,
        wH + WOFF_R2, wL + WOFF_R2, 256, 256, 0,
        b_r2, nullptr, nullptr, nullptr, t2, nullptr, nullptr);
    grid_barrier();

    // reduce: out[b,j] = sum_n t2[b,n,j]
    const int gid = (blockIdx.y * 2 + blockIdx.x) * 256 + threadIdx.x;
    if (gid < ROWS) {
        const int b = gid >> 8, j = gid & 255;
        const float* p = t2 + (size_t)b * (Nn * Hn) + j;
        float acc = 0.0f;
        for (int n = 0; n < Nn; n++) acc += ldcg1(p + (size_t)n * Hn);
        out[gid] = acc;
    }
}

// ---------------- prep kernels (separate launches; L1 flushed between) --------
__global__ void split_plain(const float* __restrict__ src, int n4, f16* __restrict__ hi, f16* __restrict__ lo)
{
    const int i = blockIdx.x * 256 + threadIdx.x;
    if (i < n4) {
        float4 v = *(const float4*)(src + i * 4);
        store_planes(hi, lo, (size_t)i * 4, v);
    }
}

__global__ void build_zrB(const float* __restrict__ Wz, const float* __restrict__ Wr,
                          const float* __restrict__ Uz, const float* __restrict__ Ur,
                          f16* __restrict__ hi, f16* __restrict__ lo)
{
    const int i = blockIdx.x * 256 + threadIdx.x;
    const int k = i >> 9, c = i & 511;
    float v;
    if (k < 256) v = (c < 256) ? Wz[k * Hn + c] : Wr[k * Hn + (c - 256)];
    else         v = (c < 256) ? Uz[(k - 256) * Hn + c] : Ur[(k - 256) * Hn + (c - 256)];
    f16 h, l; split1(v, h, l);
    hi[i] = h; lo[i] = l;
}

__global__ void build_hB(const float* __restrict__ Wh, const float* __restrict__ Uh,
                         f16* __restrict__ hi, f16* __restrict__ lo)
{
    const int i = blockIdx.x * 256 + threadIdx.x;
    const int k = i >> 8, c = i & 255;
    float v = (k < 256) ? Wh[k * Hn + c] : Uh[(k - 256) * Hn + c];
    f16 h, l; split1(v, h, l);
    hi[i] = h; lo[i] = l;
}

__global__ void emb_kernel(const float* __restrict__ jets, const float* __restrict__ W_emb,
                           const float* __restrict__ b_emb, float* __restrict__ h,
                           f16* __restrict__ hPh)
{
    const int row = blockIdx.x, j = threadIdx.x;
    __shared__ float sj[Fn];
    if (j < Fn) sj[j] = jets[(size_t)row * Fn + j];
    __syncthreads();
    float acc = b_emb[j];
    #pragma unroll
    for (int k = 0; k < Fn; k++) acc = fmaf(sj[k], W_emb[k * Hn + j], acc);
    const float v = tanhf(acc);
    const size_t idx = (size_t)row * Hn + j;
    h[idx] = v;
    hPh[idx] = __float2half_rn(v);
}

__global__ void jc_kernel(const float* __restrict__ jets,
                          const float* __restrict__ Wz, const float* __restrict__ Wr,
                          const float* __restrict__ Wh,
                          const float* __restrict__ bz, const float* __restrict__ br,
                          const float* __restrict__ bh,
                          float* jcz, float* jcr, float* jch)
{
    const int row = blockIdx.x, j = threadIdx.x;
    __shared__ float sj[Fn];
    if (j < Fn) sj[j] = jets[(size_t)row * Fn + j];
    __syncthreads();
    float az = bz[j], ar = br[j], ah = bh[j];
    #pragma unroll
    for (int k = 0; k < Fn; k++) {
        const float s = sj[k];
        const int widx = (Hn + k) * Hn + j;
        az = fmaf(s, Wz[widx], az);
        ar = fmaf(s, Wr[widx], ar);
        ah = fmaf(s, Wh[widx], ah);
    }
    const size_t idx = (size_t)row * Hn + j;
    jcz[idx] = az; jcr[idx] = ar; jch[idx] = ah;
}

// ---------------- launch ----------------
extern "C" void kernel_launch(void* const* d_in, const int* in_sizes, int n_in,
                              void* d_out, int out_size)
{
    const float* jets  = (const float*)d_in[0];
    const float* dads  = (const float*)d_in[1];
    const float* W_emb = (const float*)d_in[2];
    const float* b_emb = (const float*)d_in[3];
    const float* W_msg = (const float*)d_in[4];
    const float* b_msg = (const float*)d_in[5];
    const float* Wz    = (const float*)d_in[6];
    const float* Uz    = (const float*)d_in[7];
    const float* bz    = (const float*)d_in[8];
    const float* Wr    = (const float*)d_in[9];
    const float* Ur    = (const float*)d_in[10];
    const float* br    = (const float*)d_in[11];
    const float* Wh    = (const float*)d_in[12];
    const float* Uh    = (const float*)d_in[13];
    const float* bh    = (const float*)d_in[14];
    const float* W_r1  = (const float*)d_in[15];
    const float* b_r1  = (const float*)d_in[16];
    const float* W_r2  = (const float*)d_in[17];
    const float* b_r2  = (const float*)d_in[18];
    float* out = (float*)d_out;

    float *h, *jcz, *jcr, *jch;
    f16 *hP, *daP, *wH, *wL;
    cudaGetSymbolAddress((void**)&h,   g_h);
    cudaGetSymbolAddress((void**)&jcz, g_jcz);
    cudaGetSymbolAddress((void**)&jcr, g_jcr);
    cudaGetSymbolAddress((void**)&jch, g_jch);
    cudaGetSymbolAddress((void**)&hP,  g_hP);
    cudaGetSymbolAddress((void**)&daP, g_daP);
    cudaGetSymbolAddress((void**)&wH,  g_wH);
    cudaGetSymbolAddress((void**)&wL,  g_wL);

    static bool attr_done = false;
    if (!attr_done) {
        cudaFuncSetAttribute(mpnn_persist, cudaFuncAttributeMaxDynamicSharedMemorySize, SMEM_BYTES);
        attr_done = true;
    }

    // prep
    split_plain<<<PLANE/4/256, 256>>>(dads, PLANE/4, daP, daP + PLANE);
    split_plain<<<65536/4/256, 256>>>(W_msg, 65536/4, wH + WOFF_MSG, wL + WOFF_MSG);
    split_plain<<<65536/4/256, 256>>>(W_r1,  65536/4, wH + WOFF_R1,  wL + WOFF_R1);
    split_plain<<<65536/4/256, 256>>>(W_r2,  65536/4, wH + WOFF_R2,  wL + WOFF_R2);
    build_zrB<<<262144/256, 256>>>(Wz, Wr, Uz, Ur, wH + WOFF_ZR, wL + WOFF_ZR);
    build_hB<<<131072/256, 256>>>(Wh, Uh, wH + WOFF_HB, wL + WOFF_HB);
    emb_kernel<<<ROWS, Hn>>>(jets, W_emb, b_emb, h, hP);
    jc_kernel<<<ROWS, Hn>>>(jets, Wz, Wr, Wh, bz, br, bh, jcz, jcr, jch);

    // entire MPNN loop + readout + reduce in ONE persistent kernel
    mpnn_persist<<<dim3(2, ROWS/128), 256, SMEM_BYTES>>>(b_msg, b_r1, b_r2, out);
}

// round 14
// speedup vs baseline: 1.3034x; 1.3034x over previous
#include <cuda_runtime.h>
#include <cuda_fp16.h>
#include <cstdint>
#include <math.h>

typedef __half f16;

// ---------------- problem dims ----------------
#define Bn 64
#define Nn 256
#define Fn 16
#define Hn 256
#define ROWS (Bn*Nn)          // 16384
#define N_ITERS 10
#define PLANE (ROWS*Hn)       // 4194304

// ---------------- scratch ----------------
__device__ float g_h  [PLANE];
__device__ float g_z  [PLANE];
__device__ float g_jcz[PLANE];
__device__ float g_jcr[PLANE];
__device__ float g_jch[PLANE];
__device__ float g_t1 [PLANE];    // fp32 tanh(h@W_r1+b_r1)
__device__ float g_s  [Bn*Hn];    // node-summed readout
__device__ f16 g_hP [PLANE];
__device__ f16 g_tP [PLANE];
__device__ f16 g_mP [PLANE];
__device__ f16 g_rhP[PLANE];
__device__ f16 g_daP[PLANE];
#define WOFF_MSG 0
#define WOFF_ZR  65536
#define WOFF_HB  327680
#define WOFF_R1  458752
#define WTOTAL   524288
__device__ f16 g_wH[WTOTAL];

__device__ __forceinline__ float sigf(float x) { return 1.0f / (1.0f + expf(-x)); }

__device__ __forceinline__ uint32_t smem_u32(const void* p) {
    return (uint32_t)__cvta_generic_to_shared(p);
}
#define CP16(dst, src) asm volatile("cp.async.cg.shared.global [%0], [%1], 16;" :: "r"(dst), "l"(src))
#define CP_COMMIT()    asm volatile("cp.async.commit_group;" ::: "memory")
#define CP_WAIT(n)     asm volatile("cp.async.wait_group %0;" :: "n"(n) : "memory")

__device__ __forceinline__ void store_hi2(f16* Ph, size_t idx, float2 v) {
    __half2 h = __floats2half2_rn(v.x, v.y);
    *(uint32_t*)(Ph + idx) = *(uint32_t*)&h;
}

// ---------------- raw mma helpers ----------------
__device__ __forceinline__ void ldsm4(uint32_t addr, uint32_t& r0, uint32_t& r1, uint32_t& r2, uint32_t& r3) {
    asm volatile("ldmatrix.sync.aligned.m8n8.x4.shared.b16 {%0,%1,%2,%3}, [%4];"
                 : "=r"(r0), "=r"(r1), "=r"(r2), "=r"(r3) : "r"(addr));
}
__device__ __forceinline__ void ldsm4t(uint32_t addr, uint32_t& r0, uint32_t& r1, uint32_t& r2, uint32_t& r3) {
    asm volatile("ldmatrix.sync.aligned.m8n8.x4.trans.shared.b16 {%0,%1,%2,%3}, [%4];"
                 : "=r"(r0), "=r"(r1), "=r"(r2), "=r"(r3) : "r"(addr));
}
__device__ __forceinline__ void mma16816(float* d, const uint32_t* a, const uint32_t* b) {
    asm volatile("mma.sync.aligned.m16n8k16.row.col.f32.f16.f16.f32 "
                 "{%0,%1,%2,%3}, {%4,%5,%6,%7}, {%8,%9}, {%0,%1,%2,%3};"
                 : "+f"(d[0]), "+f"(d[1]), "+f"(d[2]), "+f"(d[3])
                 : "r"(a[0]), "r"(a[1]), "r"(a[2]), "r"(a[3]), "r"(b[0]), "r"(b[1]));
}

// ---------------- GEMM: 128x128 tile, raw mma, plain fp16 single pass ------
enum { EPI_T = 0, EPI_M, EPI_Z, EPI_R, EPI_GRU, EPI_R1 };

#define STAGES 3
#define LDA 40
#define LDB 136
#define A_OFF 0
#define B_OFF 10240            // 128*LDA*2
#define STAGE_BYTES 18944      // + 32*LDB*2 = 8704
#define SMEM_BYTES (STAGES*STAGE_BYTES)   // 56832 (x2 CTA/SM = 113664)

template<int EPI>
__global__ void __launch_bounds__(256, 2)
tc_gemm(const f16* __restrict__ A0, const f16* __restrict__ A1,
        const f16* __restrict__ B,
        int NB, int K, int batched,
        const float* __restrict__ bias,
        const float* __restrict__ jc,
        const float* __restrict__ Hb,  const float* __restrict__ Zb,
        float* Cf, f16* Ch)
{
    extern __shared__ char sm[];
    const uint32_t smaddr = smem_u32(sm);

    const int tid = threadIdx.x, wid = tid >> 5, lane = tid & 31;
    const int bn = blockIdx.x * 128, bm = blockIdx.y * 128;
    const int warp_m = wid >> 2;
    const int warp_n = wid & 3;

    int am = bm;
    size_t aoff = 0, boff = 0;
    if (batched) {
        const int b = bm >> 8;
        aoff = (size_t)b * (Nn * Hn);
        boff = (size_t)b * (Nn * Hn);
        am = bm & (Nn - 1);
    }

    const int NC = K >> 5;

    auto issue = [&](int kb) {
        const uint32_t sb = smaddr + (kb % STAGES) * STAGE_BYTES;
        const int kk = (kb & 7) * 32;
        const f16* ap; int arow;
        if (kb < 8) { ap = A0 + aoff; arow = am; }
        else        { ap = A1;        arow = bm; }
        #pragma unroll
        for (int i = 0; i < 2; i++) {
            const int c = tid + i * 256;
            {
                const int r = c >> 2, c8 = (c & 3) * 8;
                CP16(sb + A_OFF + (uint32_t)(r * LDA + c8) * 2,
                     ap + (size_t)(arow + r) * Hn + kk + c8);
            }
            {
                const int r = c >> 4, c8 = (c & 15) * 8;
                CP16(sb + B_OFF + (uint32_t)(r * LDB + c8) * 2,
                     B + boff + (size_t)(kb * 32 + r) * NB + bn + c8);
            }
        }
    };

    float acc[4][4][4];
    #pragma unroll
    for (int mi = 0; mi < 4; mi++)
        #pragma unroll
        for (int nj = 0; nj < 4; nj++)
            #pragma unroll
            for (int q = 0; q < 4; q++) acc[mi][nj][q] = 0.0f;

    const uint32_t a_lrow = (uint32_t)(lane & 15);
    const uint32_t a_lcol = (uint32_t)((lane >> 4) << 3);

    issue(0); CP_COMMIT();
    if (NC > 1) issue(1);
    CP_COMMIT();

    for (int kb = 0; kb < NC; kb++) {
        CP_WAIT(1);
        __syncthreads();

        if (kb + STAGES - 1 < NC) issue(kb + STAGES - 1);
        CP_COMMIT();

        const uint32_t sb = smaddr + (kb % STAGES) * STAGE_BYTES;

        #pragma unroll
        for (int kk = 0; kk < 2; kk++) {
            const uint32_t brow = (uint32_t)(kk * 16) + a_lrow;
            const uint32_t bcol0 = (uint32_t)(warp_n * 32) + a_lcol;
            uint32_t bfr[8];
            {
                const uint32_t ba = sb + B_OFF + (brow * LDB + bcol0) * 2;
                ldsm4t(ba,      bfr[0], bfr[1], bfr[2], bfr[3]);
                ldsm4t(ba + 32, bfr[4], bfr[5], bfr[6], bfr[7]);
            }
            const uint32_t arow0 = (uint32_t)(warp_m * 64) + a_lrow;
            const uint32_t acol = (uint32_t)(kk * 16) + a_lcol;
            #pragma unroll
            for (int mi = 0; mi < 4; mi++) {
                uint32_t a[4];
                ldsm4(sb + A_OFF + ((arow0 + mi * 16) * LDA + acol) * 2, a[0], a[1], a[2], a[3]);
                #pragma unroll
                for (int nj = 0; nj < 4; nj++) mma16816(acc[mi][nj], a, &bfr[nj * 2]);
            }
        }
    }

    // ---------------- register-direct epilogue ----------------
    const int r_in = lane >> 2;
    const int c_in = (lane & 3) * 2;

    #pragma unroll
    for (int mi = 0; mi < 4; mi++) {
        #pragma unroll
        for (int nj = 0; nj < 4; nj++) {
            #pragma unroll
            for (int half = 0; half < 2; half++) {
                const int row = bm + warp_m * 64 + mi * 16 + r_in + half * 8;
                const int col = bn + warp_n * 32 + nj * 8 + c_in;
                float2 v = make_float2(acc[mi][nj][half * 2], acc[mi][nj][half * 2 + 1]);
                const size_t idx = (size_t)row * Hn + col;

                if (EPI == EPI_T) {
                    float2 bv = *(const float2*)(bias + col);
                    v.x += bv.x; v.y += bv.y;
                    store_hi2(Ch, idx, v);
                } else if (EPI == EPI_M) {
                    v.x = tanhf(v.x); v.y = tanhf(v.y);
                    store_hi2(Ch, idx, v);
                } else if (EPI == EPI_Z) {
                    float2 jv = *(const float2*)(jc + idx);
                    v.x = sigf(v.x + jv.x); v.y = sigf(v.y + jv.y);
                    *(float2*)(Cf + idx) = v;
                } else if (EPI == EPI_R) {
                    float2 jv = *(const float2*)(jc + idx);
                    float2 hv = *(const float2*)(Hb + idx);
                    v.x = sigf(v.x + jv.x) * hv.x;
                    v.y = sigf(v.y + jv.y) * hv.y;
                    store_hi2(Ch, idx, v);
                } else if (EPI == EPI_GRU) {
                    float2 jv = *(const float2*)(jc + idx);
                    float2 hv = *(const float2*)(Hb + idx);
                    float2 zv = *(const float2*)(Zb + idx);
                    float t0 = tanhf(v.x + jv.x), t1 = tanhf(v.y + jv.y);
                    v.x = hv.x + zv.x * (t0 - hv.x);
                    v.y = hv.y + zv.y * (t1 - hv.y);
                    *(float2*)(Cf + idx) = v;
                    store_hi2(Ch, idx, v);
                } else if (EPI == EPI_R1) {
                    float2 bv = *(const float2*)(bias + col);
                    v.x = tanhf(v.x + bv.x); v.y = tanhf(v.y + bv.y);
                    *(float2*)(Cf + idx) = v;   // fp32 t1 for exact readout
                }
            }
        }
    }
}

// ---------------- prep kernels ----------------
__global__ void cvt_hi(const float* __restrict__ src, int n4, f16* __restrict__ hi)
{
    const int i = blockIdx.x * 256 + threadIdx.x;
    if (i < n4) {
        float4 v = *(const float4*)(src + i * 4);
        __half2 h01 = __floats2half2_rn(v.x, v.y);
        __half2 h23 = __floats2half2_rn(v.z, v.w);
        uint2 hv; hv.x = *(uint32_t*)&h01; hv.y = *(uint32_t*)&h23;
        *(uint2*)(hi + (size_t)i * 4) = hv;
    }
}

// zr B: [512][512]; k<256: [Wz|Wr] rows, k>=256: [Uz|Ur]
__global__ void build_zrB(const float* __restrict__ Wz, const float* __restrict__ Wr,
                          const float* __restrict__ Uz, const float* __restrict__ Ur,
                          f16* __restrict__ hi)
{
    const int i = blockIdx.x * 256 + threadIdx.x;
    const int k = i >> 9, c = i & 511;
    float v;
    if (k < 256) v = (c < 256) ? Wz[k * Hn + c] : Wr[k * Hn + (c - 256)];
    else         v = (c < 256) ? Uz[(k - 256) * Hn + c] : Ur[(k - 256) * Hn + (c - 256)];
    hi[i] = __float2half_rn(v);
}

__global__ void build_hB(const float* __restrict__ Wh, const float* __restrict__ Uh,
                         f16* __restrict__ hi)
{
    const int i = blockIdx.x * 256 + threadIdx.x;
    const int k = i >> 8, c = i & 255;
    float v = (k < 256) ? Wh[k * Hn + c] : Uh[(k - 256) * Hn + c];
    hi[i] = __float2half_rn(v);
}

__global__ void emb_kernel(const float* __restrict__ jets, const float* __restrict__ W_emb,
                           const float* __restrict__ b_emb, float* __restrict__ h,
                           f16* __restrict__ hPh)
{
    const int row = blockIdx.x, j = threadIdx.x;
    __shared__ float sj[Fn];
    if (j < Fn) sj[j] = jets[(size_t)row * Fn + j];
    __syncthreads();
    float acc = b_emb[j];
    #pragma unroll
    for (int k = 0; k < Fn; k++) acc = fmaf(sj[k], W_emb[k * Hn + j], acc);
    const float v = tanhf(acc);
    const size_t idx = (size_t)row * Hn + j;
    h[idx] = v;
    hPh[idx] = __float2half_rn(v);
}

__global__ void jc_kernel(const float* __restrict__ jets,
                          const float* __restrict__ Wz, const float* __restrict__ Wr,
                          const float* __restrict__ Wh,
                          const float* __restrict__ bz, const float* __restrict__ br,
                          const float* __restrict__ bh,
                          float* jcz, float* jcr, float* jch)
{
    const int row = blockIdx.x, j = threadIdx.x;
    __shared__ float sj[Fn];
    if (j < Fn) sj[j] = jets[(size_t)row * Fn + j];
    __syncthreads();
    float az = bz[j], ar = br[j], ah = bh[j];
    #pragma unroll
    for (int k = 0; k < Fn; k++) {
        const float s = sj[k];
        const int widx = (Hn + k) * Hn + j;
        az = fmaf(s, Wz[widx], az);
        ar = fmaf(s, Wr[widx], ar);
        ah = fmaf(s, Wh[widx], ah);
    }
    const size_t idx = (size_t)row * Hn + j;
    jcz[idx] = az; jcr[idx] = ar; jch[idx] = ah;
}

// s[b,j] = sum_n t1[b,n,j]
__global__ void reduce_kernel(const float* __restrict__ t1, float* __restrict__ s)
{
    const int idx = blockIdx.x * blockDim.x + threadIdx.x;  // 0..16383
    const int b = idx >> 8, j = idx & 255;
    const float* p = t1 + (size_t)b * (Nn * Hn) + j;
    float acc = 0.0f;
    for (int n = 0; n < Nn; n++) acc += p[(size_t)n * Hn];
    s[idx] = acc;
}

// out[b,j] = s[b,:] @ W_r2[:,j] + Nn*b_r2[j]   (exact fp32; tiny)
__global__ void readout_kernel(const float* __restrict__ s, const float* __restrict__ W_r2,
                               const float* __restrict__ b_r2, float* __restrict__ out)
{
    const int b = blockIdx.x, j = threadIdx.x;
    __shared__ float sr[Hn];
    sr[j] = s[(size_t)b * Hn + j];
    __syncthreads();
    float acc = (float)Nn * b_r2[j];
    #pragma unroll 8
    for (int k = 0; k < Hn; k++)
        acc = fmaf(sr[k], W_r2[k * Hn + j], acc);
    out[(size_t)b * Hn + j] = acc;
}

// ---------------- launch ----------------
extern "C" void kernel_launch(void* const* d_in, const int* in_sizes, int n_in,
                              void* d_out, int out_size)
{
    const float* jets  = (const float*)d_in[0];
    const float* dads  = (const float*)d_in[1];
    const float* W_emb = (const float*)d_in[2];
    const float* b_emb = (const float*)d_in[3];
    const float* W_msg = (const float*)d_in[4];
    const float* b_msg = (const float*)d_in[5];
    const float* Wz    = (const float*)d_in[6];
    const float* Uz    = (const float*)d_in[7];
    const float* bz    = (const float*)d_in[8];
    const float* Wr    = (const float*)d_in[9];
    const float* Ur    = (const float*)d_in[10];
    const float* br    = (const float*)d_in[11];
    const float* Wh    = (const float*)d_in[12];
    const float* Uh    = (const float*)d_in[13];
    const float* bh    = (const float*)d_in[14];
    const float* W_r1  = (const float*)d_in[15];
    const float* b_r1  = (const float*)d_in[16];
    const float* W_r2  = (const float*)d_in[17];
    const float* b_r2  = (const float*)d_in[18];
    float* out = (float*)d_out;

    float *h, *z, *jcz, *jcr, *jch, *t1, *s;
    f16 *hP, *tP, *mP, *rhP, *daP, *wH;
    cudaGetSymbolAddress((void**)&h,   g_h);
    cudaGetSymbolAddress((void**)&z,   g_z);
    cudaGetSymbolAddress((void**)&jcz, g_jcz);
    cudaGetSymbolAddress((void**)&jcr, g_jcr);
    cudaGetSymbolAddress((void**)&jch, g_jch);
    cudaGetSymbolAddress((void**)&t1,  g_t1);
    cudaGetSymbolAddress((void**)&s,   g_s);
    cudaGetSymbolAddress((void**)&hP,  g_hP);
    cudaGetSymbolAddress((void**)&tP,  g_tP);
    cudaGetSymbolAddress((void**)&mP,  g_mP);
    cudaGetSymbolAddress((void**)&rhP, g_rhP);
    cudaGetSymbolAddress((void**)&daP, g_daP);
    cudaGetSymbolAddress((void**)&wH,  g_wH);

    static bool attr_done = false;
    if (!attr_done) {
        cudaFuncSetAttribute(tc_gemm<EPI_T>,   cudaFuncAttributeMaxDynamicSharedMemorySize, SMEM_BYTES);
        cudaFuncSetAttribute(tc_gemm<EPI_M>,   cudaFuncAttributeMaxDynamicSharedMemorySize, SMEM_BYTES);
        cudaFuncSetAttribute(tc_gemm<EPI_Z>,   cudaFuncAttributeMaxDynamicSharedMemorySize, SMEM_BYTES);
        cudaFuncSetAttribute(tc_gemm<EPI_R>,   cudaFuncAttributeMaxDynamicSharedMemorySize, SMEM_BYTES);
        cudaFuncSetAttribute(tc_gemm<EPI_GRU>, cudaFuncAttributeMaxDynamicSharedMemorySize, SMEM_BYTES);
        cudaFuncSetAttribute(tc_gemm<EPI_R1>,  cudaFuncAttributeMaxDynamicSharedMemorySize, SMEM_BYTES);
        attr_done = true;
    }

    // prep (hi planes only — everything is 1-pass fp16 now)
    cvt_hi<<<PLANE/4/256, 256>>>(dads, PLANE/4, daP);
    cvt_hi<<<65536/4/256, 256>>>(W_msg, 65536/4, wH + WOFF_MSG);
    cvt_hi<<<65536/4/256, 256>>>(W_r1,  65536/4, wH + WOFF_R1);
    build_zrB<<<262144/256, 256>>>(Wz, Wr, Uz, Ur, wH + WOFF_ZR);
    build_hB<<<131072/256, 256>>>(Wh, Uh, wH + WOFF_HB);
    emb_kernel<<<ROWS, Hn>>>(jets, W_emb, b_emb, h, hP);
    jc_kernel<<<ROWS, Hn>>>(jets, Wz, Wr, Wh, bz, br, bh, jcz, jcr, jch);

    dim3 grid2(2, ROWS/128);   // 256 CTAs = exactly one wave at 2 CTA/SM
    for (int it = 0; it < N_ITERS; it++) {
        // t = h @ W_msg + b_msg
        tc_gemm<EPI_T><<<grid2, 256, SMEM_BYTES>>>(
            hP, nullptr, wH + WOFF_MSG, 256, 256, 0,
            b_msg, nullptr, nullptr, nullptr, nullptr, tP);
        // m = tanh(dads @ t)   (batched)
        tc_gemm<EPI_M><<<grid2, 256, SMEM_BYTES>>>(
            daP, nullptr, tP, 256, 256, 1,
            nullptr, nullptr, nullptr, nullptr, nullptr, mP);
        // z = sigmoid([m|h] @ [Wz;Uz] + jcz)
        tc_gemm<EPI_Z><<<grid2, 256, SMEM_BYTES>>>(
            mP, hP, wH + WOFF_ZR, 512, 512, 0,
            nullptr, jcz, nullptr, nullptr, z, nullptr);
        // rh = sigmoid([m|h] @ [Wr;Ur] + jcr) * h
        tc_gemm<EPI_R><<<grid2, 256, SMEM_BYTES>>>(
            mP, hP, wH + WOFF_ZR + 256, 512, 512, 0,
            nullptr, jcr, h, nullptr, nullptr, rhP);
        // h = (1-z)*h + z*tanh([m|rh] @ [Wh;Uh] + jch)
        tc_gemm<EPI_GRU><<<grid2, 256, SMEM_BYTES>>>(
            mP, rhP, wH + WOFF_HB, 256, 512, 0,
            nullptr, jch, h, z, h, hP);
    }

    // readout: t1 = tanh(h@W_r1 + b_r1) in fp32; s = sum_n t1; out = s@W_r2 + Nn*b_r2
    tc_gemm<EPI_R1><<<grid2, 256, SMEM_BYTES>>>(
        hP, nullptr, wH + WOFF_R1, 256, 256, 0,
        b_r1, nullptr, nullptr, nullptr, t1, nullptr);
    reduce_kernel<<<ROWS/256, 256>>>(t1, s);
    readout_kernel<<<Bn, Hn>>>(s, W_r2, b_r2, out);
}

// round 15
// speedup vs baseline: 1.3950x; 1.0703x over previous
#include <cuda_runtime.h>
#include <cuda_fp16.h>
#include <cstdint>
#include <math.h>

typedef __half f16;

// ---------------- problem dims ----------------
#define Bn 64
#define Nn 256
#define Fn 16
#define Hn 256
#define ROWS (Bn*Nn)          // 16384
#define N_ITERS 10
#define PLANE (ROWS*Hn)       // 4194304

// ---------------- scratch ----------------
__device__ float g_h  [PLANE];
__device__ float g_z  [PLANE];
__device__ float g_jcz[PLANE];
__device__ float g_jcr[PLANE];
__device__ float g_jch[PLANE];
__device__ float g_t1 [PLANE];
__device__ float g_s  [Bn*Hn];
__device__ f16 g_hP [PLANE];
__device__ f16 g_tP [PLANE];
__device__ f16 g_mP [PLANE];
__device__ f16 g_rhP[PLANE];
__device__ f16 g_daP[PLANE];
#define WOFF_MSG 0
#define WOFF_ZR  65536
#define WOFF_HB  327680
#define WOFF_R1  458752
#define WTOTAL   524288
__device__ f16 g_wH[WTOTAL];

__device__ __forceinline__ float sigf(float x) { return 1.0f / (1.0f + expf(-x)); }

__device__ __forceinline__ uint32_t smem_u32(const void* p) {
    return (uint32_t)__cvta_generic_to_shared(p);
}
#define CP16(dst, src) asm volatile("cp.async.cg.shared.global [%0], [%1], 16;" :: "r"(dst), "l"(src))
#define CP_COMMIT()    asm volatile("cp.async.commit_group;" ::: "memory")
#define CP_WAIT(n)     asm volatile("cp.async.wait_group %0;" :: "n"(n) : "memory")
#define GDC_WAIT()     asm volatile("griddepcontrol.wait;" ::: "memory")
#define GDC_LAUNCH()   asm volatile("griddepcontrol.launch_dependents;")

__device__ __forceinline__ void store_hi2(f16* Ph, size_t idx, float2 v) {
    __half2 h = __floats2half2_rn(v.x, v.y);
    *(uint32_t*)(Ph + idx) = *(uint32_t*)&h;
}

// ---------------- raw mma helpers ----------------
__device__ __forceinline__ void ldsm4(uint32_t addr, uint32_t& r0, uint32_t& r1, uint32_t& r2, uint32_t& r3) {
    asm volatile("ldmatrix.sync.aligned.m8n8.x4.shared.b16 {%0,%1,%2,%3}, [%4];"
                 : "=r"(r0), "=r"(r1), "=r"(r2), "=r"(r3) : "r"(addr));
}
__device__ __forceinline__ void ldsm4t(uint32_t addr, uint32_t& r0, uint32_t& r1, uint32_t& r2, uint32_t& r3) {
    asm volatile("ldmatrix.sync.aligned.m8n8.x4.trans.shared.b16 {%0,%1,%2,%3}, [%4];"
                 : "=r"(r0), "=r"(r1), "=r"(r2), "=r"(r3) : "r"(addr));
}
__device__ __forceinline__ void mma16816(float* d, const uint32_t* a, const uint32_t* b) {
    asm volatile("mma.sync.aligned.m16n8k16.row.col.f32.f16.f16.f32 "
                 "{%0,%1,%2,%3}, {%4,%5,%6,%7}, {%8,%9}, {%0,%1,%2,%3};"
                 : "+f"(d[0]), "+f"(d[1]), "+f"(d[2]), "+f"(d[3])
                 : "r"(a[0]), "r"(a[1]), "r"(a[2]), "r"(a[3]), "r"(b[0]), "r"(b[1]));
}

// ---------------- GEMM: 128x128 tile, raw mma, fp16, PDL-overlapped ------
enum { EPI_T = 0, EPI_M, EPI_Z, EPI_R, EPI_GRU, EPI_R1 };

#define STAGES 3
#define LDA 40
#define LDB 136
#define A_OFF 0
#define B_OFF 10240
#define STAGE_BYTES 18944
#define SMEM_BYTES (STAGES*STAGE_BYTES)   // 56832 (x2 CTA/SM fits)

// PRE_A/PRE_B: operand safe to prefetch before griddepcontrol.wait.
// TAILWAIT: kernel has no data dependency on predecessor; wait only at end
//           (so successor's wait transitively covers predecessor).
template<int EPI, bool PRE_A, bool PRE_B, bool TAILWAIT>
__global__ void __launch_bounds__(256, 2)
tc_gemm(const f16* __restrict__ A0, const f16* __restrict__ A1,
        const f16* __restrict__ B,
        int NB, int K, int batched,
        const float* __restrict__ bias,
        const float* __restrict__ jc,
        const float* __restrict__ Hb,  const float* __restrict__ Zb,
        float* Cf, f16* Ch)
{
    extern __shared__ char sm[];
    const uint32_t smaddr = smem_u32(sm);

    const int tid = threadIdx.x, wid = tid >> 5, lane = tid & 31;
    const int bn = blockIdx.x * 128, bm = blockIdx.y * 128;
    const int warp_m = wid >> 2;
    const int warp_n = wid & 3;

    int am = bm;
    size_t aoff = 0, boff = 0;
    if (batched) {
        const int b = bm >> 8;
        aoff = (size_t)b * (Nn * Hn);
        boff = (size_t)b * (Nn * Hn);
        am = bm & (Nn - 1);
    }

    const int NC = K >> 5;

    auto issueA = [&](int kb) {
        const uint32_t sb = smaddr + (kb % STAGES) * STAGE_BYTES;
        const int kk = (kb & 7) * 32;
        const f16* ap; int arow;
        if (kb < 8) { ap = A0 + aoff; arow = am; }
        else        { ap = A1;        arow = bm; }
        #pragma unroll
        for (int i = 0; i < 2; i++) {
            const int c = tid + i * 256;
            const int r = c >> 2, c8 = (c & 3) * 8;
            CP16(sb + A_OFF + (uint32_t)(r * LDA + c8) * 2,
                 ap + (size_t)(arow + r) * Hn + kk + c8);
        }
    };
    auto issueB = [&](int kb) {
        const uint32_t sb = smaddr + (kb % STAGES) * STAGE_BYTES;
        #pragma unroll
        for (int i = 0; i < 2; i++) {
            const int c = tid + i * 256;
            const int r = c >> 4, c8 = (c & 15) * 8;
            CP16(sb + B_OFF + (uint32_t)(r * LDB + c8) * 2,
                 B + boff + (size_t)(kb * 32 + r) * NB + bn + c8);
        }
    };

    float acc[4][4][4];
    #pragma unroll
    for (int mi = 0; mi < 4; mi++)
        #pragma unroll
        for (int nj = 0; nj < 4; nj++)
            #pragma unroll
            for (int q = 0; q < 4; q++) acc[mi][nj][q] = 0.0f;

    const uint32_t a_lrow = (uint32_t)(lane & 15);
    const uint32_t a_lcol = (uint32_t)((lane >> 4) << 3);

    // -------- PDL-aware prologue --------
    if (PRE_A) { issueA(0); issueA(1); }
    if (PRE_B) { issueB(0); issueB(1); }
    CP_COMMIT();                        // group 0: pre-wait loads
    if (!TAILWAIT) GDC_WAIT();          // predecessor complete
    GDC_LAUNCH();                       // successor may launch + prefetch
    if (!PRE_A) issueA(0);
    if (!PRE_B) issueB(0);
    CP_COMMIT();                        // group 1: chunk 0 remainder
    if (NC > 1) { if (!PRE_A) issueA(1); if (!PRE_B) issueB(1); }
    CP_COMMIT();                        // group 2: chunk 1 remainder

    for (int kb = 0; kb < NC; kb++) {
        CP_WAIT(1);                     // all but newest group landed
        __syncthreads();

        if (kb + STAGES - 1 < NC) { issueA(kb + STAGES - 1); issueB(kb + STAGES - 1); }
        CP_COMMIT();

        const uint32_t sb = smaddr + (kb % STAGES) * STAGE_BYTES;

        #pragma unroll
        for (int kk = 0; kk < 2; kk++) {
            const uint32_t brow = (uint32_t)(kk * 16) + a_lrow;
            const uint32_t bcol0 = (uint32_t)(warp_n * 32) + a_lcol;
            uint32_t bfr[8];
            {
                const uint32_t ba = sb + B_OFF + (brow * LDB + bcol0) * 2;
                ldsm4t(ba,      bfr[0], bfr[1], bfr[2], bfr[3]);
                ldsm4t(ba + 32, bfr[4], bfr[5], bfr[6], bfr[7]);
            }
            const uint32_t arow0 = (uint32_t)(warp_m * 64) + a_lrow;
            const uint32_t acol = (uint32_t)(kk * 16) + a_lcol;
            #pragma unroll
            for (int mi = 0; mi < 4; mi++) {
                uint32_t a[4];
                ldsm4(sb + A_OFF + ((arow0 + mi * 16) * LDA + acol) * 2, a[0], a[1], a[2], a[3]);
                #pragma unroll
                for (int nj = 0; nj < 4; nj++) mma16816(acc[mi][nj], a, &bfr[nj * 2]);
            }
        }
    }

    // ---------------- register-direct epilogue ----------------
    const int r_in = lane >> 2;
    const int c_in = (lane & 3) * 2;

    #pragma unroll
    for (int mi = 0; mi < 4; mi++) {
        #pragma unroll
        for (int nj = 0; nj < 4; nj++) {
            #pragma unroll
            for (int half = 0; half < 2; half++) {
                const int row = bm + warp_m * 64 + mi * 16 + r_in + half * 8;
                const int col = bn + warp_n * 32 + nj * 8 + c_in;
                float2 v = make_float2(acc[mi][nj][half * 2], acc[mi][nj][half * 2 + 1]);
                const size_t idx = (size_t)row * Hn + col;

                if (EPI == EPI_T) {
                    float2 bv = *(const float2*)(bias + col);
                    v.x += bv.x; v.y += bv.y;
                    store_hi2(Ch, idx, v);
                } else if (EPI == EPI_M) {
                    v.x = tanhf(v.x); v.y = tanhf(v.y);
                    store_hi2(Ch, idx, v);
                } else if (EPI == EPI_Z) {
                    float2 jv = *(const float2*)(jc + idx);
                    v.x = sigf(v.x + jv.x); v.y = sigf(v.y + jv.y);
                    *(float2*)(Cf + idx) = v;
                } else if (EPI == EPI_R) {
                    float2 jv = *(const float2*)(jc + idx);
                    float2 hv = *(const float2*)(Hb + idx);
                    v.x = sigf(v.x + jv.x) * hv.x;
                    v.y = sigf(v.y + jv.y) * hv.y;
                    store_hi2(Ch, idx, v);
                } else if (EPI == EPI_GRU) {
                    float2 jv = *(const float2*)(jc + idx);
                    float2 hv = *(const float2*)(Hb + idx);
                    float2 zv = *(const float2*)(Zb + idx);
                    float t0 = tanhf(v.x + jv.x), t1 = tanhf(v.y + jv.y);
                    v.x = hv.x + zv.x * (t0 - hv.x);
                    v.y = hv.y + zv.y * (t1 - hv.y);
                    *(float2*)(Cf + idx) = v;
                    store_hi2(Ch, idx, v);
                } else if (EPI == EPI_R1) {
                    float2 bv = *(const float2*)(bias + col);
                    v.x = tanhf(v.x + bv.x); v.y = tanhf(v.y + bv.y);
                    *(float2*)(Cf + idx) = v;
                }
            }
        }
    }

    if (TAILWAIT) GDC_WAIT();   // complete no earlier than predecessor
}

// ---------------- prep kernels ----------------
__global__ void cvt_hi(const float* __restrict__ src, int n4, f16* __restrict__ hi)
{
    const int i = blockIdx.x * 256 + threadIdx.x;
    if (i < n4) {
        float4 v = *(const float4*)(src + i * 4);
        __half2 h01 = __floats2half2_rn(v.x, v.y);
        __half2 h23 = __floats2half2_rn(v.z, v.w);
        uint2 hv; hv.x = *(uint32_t*)&h01; hv.y = *(uint32_t*)&h23;
        *(uint2*)(hi + (size_t)i * 4) = hv;
    }
}

__global__ void build_zrB(const float* __restrict__ Wz, const float* __restrict__ Wr,
                          const float* __restrict__ Uz, const float* __restrict__ Ur,
                          f16* __restrict__ hi)
{
    const int i = blockIdx.x * 256 + threadIdx.x;
    const int k = i >> 9, c = i & 511;
    float v;
    if (k < 256) v = (c < 256) ? Wz[k * Hn + c] : Wr[k * Hn + (c - 256)];
    else         v = (c < 256) ? Uz[(k - 256) * Hn + c] : Ur[(k - 256) * Hn + (c - 256)];
    hi[i] = __float2half_rn(v);
}

__global__ void build_hB(const float* __restrict__ Wh, const float* __restrict__ Uh,
                         f16* __restrict__ hi)
{
    const int i = blockIdx.x * 256 + threadIdx.x;
    const int k = i >> 8, c = i & 255;
    float v = (k < 256) ? Wh[k * Hn + c] : Uh[(k - 256) * Hn + c];
    hi[i] = __float2half_rn(v);
}

__global__ void emb_kernel(const float* __restrict__ jets, const float* __restrict__ W_emb,
                           const float* __restrict__ b_emb, float* __restrict__ h,
                           f16* __restrict__ hPh)
{
    const int row = blockIdx.x, j = threadIdx.x;
    __shared__ float sj[Fn];
    if (j < Fn) sj[j] = jets[(size_t)row * Fn + j];
    __syncthreads();
    float acc = b_emb[j];
    #pragma unroll
    for (int k = 0; k < Fn; k++) acc = fmaf(sj[k], W_emb[k * Hn + j], acc);
    const float v = tanhf(acc);
    const size_t idx = (size_t)row * Hn + j;
    h[idx] = v;
    hPh[idx] = __float2half_rn(v);
}

__global__ void jc_kernel(const float* __restrict__ jets,
                          const float* __restrict__ Wz, const float* __restrict__ Wr,
                          const float* __restrict__ Wh,
                          const float* __restrict__ bz, const float* __restrict__ br,
                          const float* __restrict__ bh,
                          float* jcz, float* jcr, float* jch)
{
    const int row = blockIdx.x, j = threadIdx.x;
    __shared__ float sj[Fn];
    if (j < Fn) sj[j] = jets[(size_t)row * Fn + j];
    __syncthreads();
    float az = bz[j], ar = br[j], ah = bh[j];
    #pragma unroll
    for (int k = 0; k < Fn; k++) {
        const float s = sj[k];
        const int widx = (Hn + k) * Hn + j;
        az = fmaf(s, Wz[widx], az);
        ar = fmaf(s, Wr[widx], ar);
        ah = fmaf(s, Wh[widx], ah);
    }
    const size_t idx = (size_t)row * Hn + j;
    jcz[idx] = az; jcr[idx] = ar; jch[idx] = ah;
}

__global__ void reduce_kernel(const float* __restrict__ t1, float* __restrict__ s)
{
    const int idx = blockIdx.x * blockDim.x + threadIdx.x;
    const int b = idx >> 8, j = idx & 255;
    const float* p = t1 + (size_t)b * (Nn * Hn) + j;
    float acc = 0.0f;
    for (int n = 0; n < Nn; n++) acc += p[(size_t)n * Hn];
    s[idx] = acc;
}

__global__ void readout_kernel(const float* __restrict__ s, const float* __restrict__ W_r2,
                               const float* __restrict__ b_r2, float* __restrict__ out)
{
    const int b = blockIdx.x, j = threadIdx.x;
    __shared__ float sr[Hn];
    sr[j] = s[(size_t)b * Hn + j];
    __syncthreads();
    float acc = (float)Nn * b_r2[j];
    #pragma unroll 8
    for (int k = 0; k < Hn; k++)
        acc = fmaf(sr[k], W_r2[k * Hn + j], acc);
    out[(size_t)b * Hn + j] = acc;
}

// ---------------- launch ----------------
template<typename KF, typename... Args>
static inline void pdl_launch(KF kern, dim3 grid, Args... args)
{
    cudaLaunchConfig_t cfg = {};
    cfg.gridDim = grid;
    cfg.blockDim = dim3(256, 1, 1);
    cfg.dynamicSmemBytes = SMEM_BYTES;
    cfg.stream = 0;
    cudaLaunchAttribute at[1];
    at[0].id = cudaLaunchAttributeProgrammaticStreamSerialization;
    at[0].val.programmaticStreamSerializationAllowed = 1;
    cfg.attrs = at;
    cfg.numAttrs = 1;
    cudaLaunchKernelEx(&cfg, kern, args...);
}

extern "C" void kernel_launch(void* const* d_in, const int* in_sizes, int n_in,
                              void* d_out, int out_size)
{
    const float* jets  = (const float*)d_in[0];
    const float* dads  = (const float*)d_in[1];
    const float* W_emb = (const float*)d_in[2];
    const float* b_emb = (const float*)d_in[3];
    const float* W_msg = (const float*)d_in[4];
    const float* b_msg = (const float*)d_in[5];
    const float* Wz    = (const float*)d_in[6];
    const float* Uz    = (const float*)d_in[7];
    const float* bz    = (const float*)d_in[8];
    const float* Wr    = (const float*)d_in[9];
    const float* Ur    = (const float*)d_in[10];
    const float* br    = (const float*)d_in[11];
    const float* Wh    = (const float*)d_in[12];
    const float* Uh    = (const float*)d_in[13];
    const float* bh    = (const float*)d_in[14];
    const float* W_r1  = (const float*)d_in[15];
    const float* b_r1  = (const float*)d_in[16];
    const float* W_r2  = (const float*)d_in[17];
    const float* b_r2  = (const float*)d_in[18];
    float* out = (float*)d_out;

    float *h, *z, *jcz, *jcr, *jch, *t1, *s;
    f16 *hP, *tP, *mP, *rhP, *daP, *wH;
    cudaGetSymbolAddress((void**)&h,   g_h);
    cudaGetSymbolAddress((void**)&z,   g_z);
    cudaGetSymbolAddress((void**)&jcz, g_jcz);
    cudaGetSymbolAddress((void**)&jcr, g_jcr);
    cudaGetSymbolAddress((void**)&jch, g_jch);
    cudaGetSymbolAddress((void**)&t1,  g_t1);
    cudaGetSymbolAddress((void**)&s,   g_s);
    cudaGetSymbolAddress((void**)&hP,  g_hP);
    cudaGetSymbolAddress((void**)&tP,  g_tP);
    cudaGetSymbolAddress((void**)&mP,  g_mP);
    cudaGetSymbolAddress((void**)&rhP, g_rhP);
    cudaGetSymbolAddress((void**)&daP, g_daP);
    cudaGetSymbolAddress((void**)&wH,  g_wH);

    static bool attr_done = false;
    if (!attr_done) {
        cudaFuncSetAttribute(tc_gemm<EPI_T,false,true,false>,  cudaFuncAttributeMaxDynamicSharedMemorySize, SMEM_BYTES);
        cudaFuncSetAttribute(tc_gemm<EPI_M,true,false,false>,  cudaFuncAttributeMaxDynamicSharedMemorySize, SMEM_BYTES);
        cudaFuncSetAttribute(tc_gemm<EPI_Z,false,true,false>,  cudaFuncAttributeMaxDynamicSharedMemorySize, SMEM_BYTES);
        cudaFuncSetAttribute(tc_gemm<EPI_R,true,true,true>,    cudaFuncAttributeMaxDynamicSharedMemorySize, SMEM_BYTES);
        cudaFuncSetAttribute(tc_gemm<EPI_GRU,true,true,false>, cudaFuncAttributeMaxDynamicSharedMemorySize, SMEM_BYTES);
        cudaFuncSetAttribute(tc_gemm<EPI_R1,false,true,false>, cudaFuncAttributeMaxDynamicSharedMemorySize, SMEM_BYTES);
        attr_done = true;
    }

    // prep
    cvt_hi<<<PLANE/4/256, 256>>>(dads, PLANE/4, daP);
    cvt_hi<<<65536/4/256, 256>>>(W_msg, 65536/4, wH + WOFF_MSG);
    cvt_hi<<<65536/4/256, 256>>>(W_r1,  65536/4, wH + WOFF_R1);
    build_zrB<<<262144/256, 256>>>(Wz, Wr, Uz, Ur, wH + WOFF_ZR);
    build_hB<<<131072/256, 256>>>(Wh, Uh, wH + WOFF_HB);
    emb_kernel<<<ROWS, Hn>>>(jets, W_emb, b_emb, h, hP);
    jc_kernel<<<ROWS, Hn>>>(jets, Wz, Wr, Wh, bz, br, bh, jcz, jcr, jch);

    dim3 grid2(2, ROWS/128);   // 256 CTAs = one wave at 2 CTA/SM
    for (int it = 0; it < N_ITERS; it++) {
        // t = h @ W_msg + b_msg          (A=hP dep of GRU; B weights pre)
        pdl_launch(tc_gemm<EPI_T,false,true,false>, grid2,
            hP, (const f16*)nullptr, (const f16*)(wH + WOFF_MSG), 256, 256, 0,
            b_msg, (const float*)nullptr, (const float*)nullptr, (const float*)nullptr,
            (float*)nullptr, tP);
        // m = tanh(dads @ t)             (A=daP const pre; B=tP dep of T)
        pdl_launch(tc_gemm<EPI_M,true,false,false>, grid2,
            daP, (const f16*)nullptr, tP, 256, 256, 1,
            (const float*)nullptr, (const float*)nullptr, (const float*)nullptr, (const float*)nullptr,
            (float*)nullptr, mP);
        // z = sigmoid([m|h]@[Wz;Uz]+jcz) (A=mP dep of M; B weights pre)
        pdl_launch(tc_gemm<EPI_Z,false,true,false>, grid2,
            mP, hP, (const f16*)(wH + WOFF_ZR), 512, 512, 0,
            (const float*)nullptr, jcz, (const float*)nullptr, (const float*)nullptr,
            z, (f16*)nullptr);
        // rh = sigmoid([m|h]@[Wr;Ur]+jcr)*h  (no dep on Z: prefetch all, wait at END)
        pdl_launch(tc_gemm<EPI_R,true,true,true>, grid2,
            mP, hP, (const f16*)(wH + WOFF_ZR + 256), 512, 512, 0,
            (const float*)nullptr, jcr, h, (const float*)nullptr,
            (float*)nullptr, rhP);
        // h = (1-z)*h + z*tanh([m|rh]@[Wh;Uh]+jch)  (mP chunks pre-safe; rh/z after wait)
        pdl_launch(tc_gemm<EPI_GRU,true,true,false>, grid2,
            mP, rhP, (const f16*)(wH + WOFF_HB), 256, 512, 0,
            (const float*)nullptr, jch, h, z,
            h, hP);
    }

    // readout
    pdl_launch(tc_gemm<EPI_R1,false,true,false>, grid2,
        hP, (const f16*)nullptr, (const f16*)(wH + WOFF_R1), 256, 256, 0,
        b_r1, (const float*)nullptr, (const float*)nullptr, (const float*)nullptr,
        t1, (f16*)nullptr);
    reduce_kernel<<<ROWS/256, 256>>>(t1, s);
    readout_kernel<<<Bn, Hn>>>(s, W_r2, b_r2, out);
}